// round 14
// baseline (speedup 1.0000x reference)
#include <cuda_runtime.h>
#include <cuda_fp16.h>
#include <cstdint>

#define N_NODES 50000
#define N_EDGES 600000
#define N_RELS  500
#define DIM     128
#define M_PAD   50048
#define NTILES  391          // ceil(50000/128)

typedef unsigned int u32;
typedef unsigned short u16;

// ---------------------------------------------------------------------------
// Device scratch (all fp16)
// ---------------------------------------------------------------------------
__device__ __align__(16) u16 g_S16[(size_t)M_PAD * DIM];      // fp16 scatter accumulator
__device__ __align__(16) u16 g_h16[(size_t)M_PAD * DIM];      // fp16 h (padded w/ zeros)
__device__ __align__(16) u16 g_rel16[N_RELS * DIM];           // fp16 rel_emb
__device__ __align__(16) u16 g_B[128 * DIM];                  // Wn fp16 [K=128][N=128]

__device__ __forceinline__ u32 pack_h2(float lo, float hi) {
    u32 r;
    asm("cvt.rn.f16x2.f32 %0, %1, %2;" : "=r"(r) : "f"(hi), "f"(lo));
    return r;
}

// ---------------------------------------------------------------------------
// Kernel 1: unified init (grid-stride): zero S16, h->fp16, rel->fp16, Wn->fp16
// ---------------------------------------------------------------------------
#define IT0 (N_NODES * DIM / 8)
#define IT1 (IT0 + M_PAD * DIM / 8)
#define IT2 (IT1 + N_RELS * DIM / 8)
#define IT3 (IT2 + 128 * DIM / 8)

__global__ void __launch_bounds__(256) init_kernel(
    const float* __restrict__ h,
    const float* __restrict__ rel_emb,
    const float* __restrict__ W_neighbor)
{
    for (int i = blockIdx.x * 256 + threadIdx.x; i < IT3; i += gridDim.x * 256) {
        if (i < IT0) {
            ((uint4*)g_S16)[i] = make_uint4(0, 0, 0, 0);
        } else if (i < IT1) {
            int j   = i - IT0;
            int row = j >> 4;
            int sg  = j & 15;
            uint4 o = make_uint4(0, 0, 0, 0);
            if (row < N_NODES) {
                const float4* src = (const float4*)(h + (size_t)row * DIM + sg * 8);
                float4 a = src[0], b = src[1];
                o.x = pack_h2(a.x, a.y); o.y = pack_h2(a.z, a.w);
                o.z = pack_h2(b.x, b.y); o.w = pack_h2(b.z, b.w);
            }
            ((uint4*)g_h16)[j] = o;
        } else if (i < IT2) {
            int j = i - IT1;
            const float4* src = (const float4*)(rel_emb + (size_t)j * 8);
            float4 a = src[0], b = src[1];
            uint4 o;
            o.x = pack_h2(a.x, a.y); o.y = pack_h2(a.z, a.w);
            o.z = pack_h2(b.x, b.y); o.w = pack_h2(b.z, b.w);
            ((uint4*)g_rel16)[j] = o;
        } else {
            int j = i - IT2;                 // < 2048
            const float* src = W_neighbor + (size_t)j * 8;
            float4 a = ((const float4*)src)[0], b = ((const float4*)src)[1];
            uint4 o;
            o.x = pack_h2(a.x, a.y); o.y = pack_h2(a.z, a.w);
            o.z = pack_h2(b.x, b.y); o.w = pack_h2(b.z, b.w);
            ((uint4*)g_B)[j] = o;
        }
    }
}

// ---------------------------------------------------------------------------
// Kernel 2: fp16 edge scatter.  16 lanes per edge (one warp = 2 edges).
// ---------------------------------------------------------------------------
__global__ void __launch_bounds__(256) scatter_edges_kernel(
    const int* __restrict__ edge_src,
    const int* __restrict__ edge_dst,
    const int* __restrict__ edge_type)
{
    int w    = (int)((blockIdx.x * (unsigned)blockDim.x + threadIdx.x) >> 5);
    int lane = threadIdx.x & 31;
    int e    = w * 2 + (lane >> 4);
    if (e >= N_EDGES) return;
    int l16 = lane & 15;

    int s = __ldg(edge_src  + e);
    int d = __ldg(edge_dst  + e);
    int t = __ldg(edge_type + e);

    const uint4 hv = *(const uint4*)(g_h16   + (size_t)s * DIM + l16 * 8);
    const uint4 rv = *(const uint4*)(g_rel16 + (size_t)t * DIM + l16 * 8);

    u32 m0, m1, m2, m3;
    asm("add.rn.f16x2 %0, %1, %2;" : "=r"(m0) : "r"(hv.x), "r"(rv.x));
    asm("add.rn.f16x2 %0, %1, %2;" : "=r"(m1) : "r"(hv.y), "r"(rv.y));
    asm("add.rn.f16x2 %0, %1, %2;" : "=r"(m2) : "r"(hv.z), "r"(rv.z));
    asm("add.rn.f16x2 %0, %1, %2;" : "=r"(m3) : "r"(hv.w), "r"(rv.w));

    u16* outp = g_S16 + (size_t)d * DIM + l16 * 8;
    asm volatile("red.global.add.noftz.v4.f16x2 [%0], {%1, %2, %3, %4};"
                 :: "l"(outp), "r"(m0), "r"(m1), "r"(m2), "r"(m3) : "memory");
}

// ---------------------------------------------------------------------------
// Shared GEMM helpers
// ---------------------------------------------------------------------------
#define A_STRIDE 144
#define B_STRIDE 272

__device__ __forceinline__ void ldsm4(u32* r, u32 addr) {
    asm volatile("ldmatrix.sync.aligned.m8n8.x4.shared.b16 {%0,%1,%2,%3}, [%4];"
                 : "=r"(r[0]), "=r"(r[1]), "=r"(r[2]), "=r"(r[3]) : "r"(addr));
}
__device__ __forceinline__ void ldsm4t(u32* r, u32 addr) {
    asm volatile("ldmatrix.sync.aligned.m8n8.x4.trans.shared.b16 {%0,%1,%2,%3}, [%4];"
                 : "=r"(r[0]), "=r"(r[1]), "=r"(r[2]), "=r"(r[3]) : "r"(addr));
}
__device__ __forceinline__ void mma16816(float* d, const u32* a, u32 b0, u32 b1) {
    asm volatile("mma.sync.aligned.m16n8k16.row.col.f32.f16.f16.f32 "
                 "{%0,%1,%2,%3}, {%4,%5,%6,%7}, {%8,%9}, {%0,%1,%2,%3};"
                 : "+f"(d[0]), "+f"(d[1]), "+f"(d[2]), "+f"(d[3])
                 : "r"(a[0]), "r"(a[1]), "r"(a[2]), "r"(a[3]), "r"(b0), "r"(b1));
}
__device__ __forceinline__ void cp16(u32 dst, const void* src) {
    asm volatile("cp.async.cg.shared.global [%0], [%1], 16;" :: "r"(dst), "l"(src) : "memory");
}
#define CP_COMMIT() asm volatile("cp.async.commit_group;" ::: "memory")

// compute one 64-K chunk: all warps, 32x64 warp tile, acc[2][8][4]
__device__ __forceinline__ void compute_chunk(
    u32 a_sm, u32 b_sm, int lane, int warp_m, int warp_n, float acc[2][8][4])
{
#pragma unroll
    for (int k16 = 0; k16 < 4; k16++) {
        u32 bh[4][4];
#pragma unroll
        for (int ng = 0; ng < 4; ng++) {
            u32 baddr = b_sm
                      + (u32)((k16 * 16 + (lane & 15)) * B_STRIDE)
                      + (u32)((warp_n * 64 + ng * 16 + (lane >> 4) * 8) * 2);
            ldsm4t(bh[ng], baddr);
        }
#pragma unroll
        for (int mi = 0; mi < 2; mi++) {
            u32 aaddr = a_sm
                      + (u32)((warp_m * 32 + mi * 16 + (lane & 15)) * A_STRIDE)
                      + (u32)(k16 * 32 + (lane >> 4) * 16);
            u32 ah[4];
            ldsm4(ah, aaddr);
#pragma unroll
            for (int ni = 0; ni < 8; ni++) {
                int ng = ni >> 1;
                int hf = (ni & 1) * 2;
                mma16816(acc[mi][ni], ah, bh[ng][hf], bh[ng][hf + 1]);
            }
        }
    }
}

// ---------------------------------------------------------------------------
// Kernel 3 (stream 2, fully independent): out = h @ loop_weight  (fp32, no relu)
// A staged from fp32 h with in-register convert; B converted in-kernel.
// smem: B [128][B_STRIDE] = 34816, A stages 2*18432 -> total 71680.
// ---------------------------------------------------------------------------
#define HB_OFF   0
#define HA_OFF(s) (34816 + (s) * 18432)
#define SM_TOTAL 71680

__device__ __forceinline__ void stage_Ah(const float* __restrict__ h,
                                         int row0, int c, int tid,
                                         char* smem, u32 a_off)
{
    int row  = tid >> 1;
    int half = tid & 1;
    int gr   = row0 + row;
    bool valid = (gr < N_NODES);
    const float* src = h + (size_t)gr * DIM + c * 64 + half * 32;
#pragma unroll
    for (int j8 = 0; j8 < 2; j8++) {      // two groups of 16 floats
        float vals[16];
        if (valid) {
#pragma unroll
            for (int q = 0; q < 4; q++) {
                float4 v = ((const float4*)src)[j8 * 4 + q];
                vals[q * 4 + 0] = v.x; vals[q * 4 + 1] = v.y;
                vals[q * 4 + 2] = v.z; vals[q * 4 + 3] = v.w;
            }
        } else {
#pragma unroll
            for (int q = 0; q < 16; q++) vals[q] = 0.f;
        }
        u32 w[8];
#pragma unroll
        for (int p = 0; p < 8; p++) w[p] = pack_h2(vals[2 * p], vals[2 * p + 1]);
        u32 off = (u32)(row * A_STRIDE + (half * 32 + j8 * 16) * 2);
        *(uint4*)(smem + a_off + off)      = make_uint4(w[0], w[1], w[2], w[3]);
        *(uint4*)(smem + a_off + off + 16) = make_uint4(w[4], w[5], w[6], w[7]);
    }
}

__global__ void __launch_bounds__(256, 2) hgemm_kernel(
    const float* __restrict__ h,
    const float* __restrict__ loop_weight,
    float* __restrict__ out)
{
    extern __shared__ char smem[];
    u32 sbase;
    asm("{ .reg .u64 t; cvta.to.shared.u64 t, %1; cvt.u32.u64 %0, t; }"
        : "=r"(sbase) : "l"(smem));

    const int tid    = threadIdx.x;
    const int wid    = tid >> 5;
    const int lane   = tid & 31;
    const int warp_m = wid & 3;
    const int warp_n = wid >> 2;
    const int row0   = blockIdx.x * 128;

    // convert loop_weight -> fp16 smem B (one pass, 256 threads = 128 rows x 2 halves)
    {
        int r  = tid >> 1;
        int hf = tid & 1;
        const float* src = loop_weight + (size_t)r * DIM + hf * 64;
        char* dst = smem + HB_OFF + r * B_STRIDE + hf * 128;
#pragma unroll
        for (int g = 0; g < 4; g++) {      // 4 groups of 16 floats
            float4 a = ((const float4*)src)[g * 4 + 0];
            float4 b = ((const float4*)src)[g * 4 + 1];
            float4 cc = ((const float4*)src)[g * 4 + 2];
            float4 d = ((const float4*)src)[g * 4 + 3];
            uint4 o;
            o.x = pack_h2(a.x, a.y); o.y = pack_h2(a.z, a.w);
            o.z = pack_h2(b.x, b.y); o.w = pack_h2(b.z, b.w);
            *(uint4*)(dst + g * 32) = o;
            uint4 o2;
            o2.x = pack_h2(cc.x, cc.y); o2.y = pack_h2(cc.z, cc.w);
            o2.z = pack_h2(d.x, d.y);   o2.w = pack_h2(d.z, d.w);
            // NOTE: 16 floats per group of 32 bytes: the above writes 2x16B = 16 f16x2 = 32 halves
            *(uint4*)(dst + g * 32 + 16) = o2;
        }
    }
    stage_Ah(h, row0, 0, tid, smem, HA_OFF(0));
    __syncthreads();

    float acc[2][8][4];
#pragma unroll
    for (int mi = 0; mi < 2; mi++)
#pragma unroll
        for (int ni = 0; ni < 8; ni++)
#pragma unroll
            for (int q = 0; q < 4; q++) acc[mi][ni][q] = 0.f;

    // chunk 0 compute; stage chunk 1 concurrently (warp-interleaved)
    compute_chunk(sbase + HA_OFF(0), sbase + HB_OFF, lane, warp_m, warp_n, acc);
    stage_Ah(h, row0, 1, tid, smem, HA_OFF(1));
    __syncthreads();
    compute_chunk(sbase + HA_OFF(1), sbase + HB_OFF + (u32)(64 * B_STRIDE),
                  lane, warp_m, warp_n, acc);

    // store raw fp32 loop message (no relu)
#pragma unroll
    for (int mi = 0; mi < 2; mi++) {
        int r0 = row0 + warp_m * 32 + mi * 16 + (lane >> 2);
#pragma unroll
        for (int ni = 0; ni < 8; ni++) {
            int col = warp_n * 64 + ni * 8 + (lane & 3) * 2;
            if (r0 < N_NODES)
                *(float2*)(out + (size_t)r0 * DIM + col) =
                    make_float2(acc[mi][ni][0], acc[mi][ni][1]);
            if (r0 + 8 < N_NODES)
                *(float2*)(out + (size_t)(r0 + 8) * DIM + col) =
                    make_float2(acc[mi][ni][2], acc[mi][ni][3]);
        }
    }
}

// ---------------------------------------------------------------------------
// Kernel 4 (default stream): out = relu( norm .* (S @ Wn) + out )
// A from g_S16 + B from g_B via cp.async, 2 chunks, double buffered.
// smem layout identical to hgemm: B chunks stacked at HB_OFF.
// ---------------------------------------------------------------------------
__device__ __forceinline__ void issue_S(u32 sbase, int tid, int row0, int c)
{
    u32 ab = sbase + HA_OFF(c);
#pragma unroll
    for (int it = 0; it < 4; it++) {
        int i  = tid + it * 256;           // < 1024
        int r  = i >> 3;
        int sg = i & 7;
        cp16(ab + (u32)(r * A_STRIDE + sg * 16),
             (const char*)(g_S16 + (size_t)(row0 + r) * DIM + c * 64) + sg * 16);
    }
    u32 bb = sbase + HB_OFF + (u32)(c * 64 * B_STRIDE);
#pragma unroll
    for (int it = 0; it < 4; it++) {
        int i  = tid + it * 256;           // < 1024
        int r  = i >> 4;
        int sg = i & 15;
        cp16(bb + (u32)(r * B_STRIDE + sg * 16),
             (const char*)g_B + (size_t)(c * 64 + r) * 256 + sg * 16);
    }
}

__global__ void __launch_bounds__(256, 2) sgemm_kernel(
    const float* __restrict__ norm,
    float* __restrict__ out)
{
    extern __shared__ char smem[];
    u32 sbase;
    asm("{ .reg .u64 t; cvta.to.shared.u64 t, %1; cvt.u32.u64 %0, t; }"
        : "=r"(sbase) : "l"(smem));

    const int tid    = threadIdx.x;
    const int wid    = tid >> 5;
    const int lane   = tid & 31;
    const int warp_m = wid & 3;
    const int warp_n = wid >> 2;
    const int row0   = blockIdx.x * 128;

    float nrm[2][2];
#pragma unroll
    for (int mi = 0; mi < 2; mi++) {
        int r0 = row0 + warp_m * 32 + mi * 16 + (lane >> 2);
        nrm[mi][0] = (r0     < N_NODES) ? __ldg(norm + r0)     : 0.f;
        nrm[mi][1] = (r0 + 8 < N_NODES) ? __ldg(norm + r0 + 8) : 0.f;
    }

    issue_S(sbase, tid, row0, 0);
    CP_COMMIT();
    issue_S(sbase, tid, row0, 1);
    CP_COMMIT();

    float acc[2][8][4];
#pragma unroll
    for (int mi = 0; mi < 2; mi++)
#pragma unroll
        for (int ni = 0; ni < 8; ni++)
#pragma unroll
            for (int q = 0; q < 4; q++) acc[mi][ni][q] = 0.f;

    asm volatile("cp.async.wait_group 1;" ::: "memory");
    __syncthreads();
    compute_chunk(sbase + HA_OFF(0), sbase + HB_OFF, lane, warp_m, warp_n, acc);
    asm volatile("cp.async.wait_group 0;" ::: "memory");
    __syncthreads();
    compute_chunk(sbase + HA_OFF(1), sbase + HB_OFF + (u32)(64 * B_STRIDE),
                  lane, warp_m, warp_n, acc);

    // epilogue: out = relu(norm*acc + out)
#pragma unroll
    for (int mi = 0; mi < 2; mi++) {
        int r0 = row0 + warp_m * 32 + mi * 16 + (lane >> 2);
#pragma unroll
        for (int ni = 0; ni < 8; ni++) {
            int col = warp_n * 64 + ni * 8 + (lane & 3) * 2;
            if (r0 < N_NODES) {
                float* p = out + (size_t)r0 * DIM + col;
                float2 lp = *(float2*)p;
                float2 v;
                v.x = fmaxf(acc[mi][ni][0] * nrm[mi][0] + lp.x, 0.f);
                v.y = fmaxf(acc[mi][ni][1] * nrm[mi][0] + lp.y, 0.f);
                *(float2*)p = v;
            }
            if (r0 + 8 < N_NODES) {
                float* p = out + (size_t)(r0 + 8) * DIM + col;
                float2 lp = *(float2*)p;
                float2 v;
                v.x = fmaxf(acc[mi][ni][2] * nrm[mi][1] + lp.x, 0.f);
                v.y = fmaxf(acc[mi][ni][3] * nrm[mi][1] + lp.y, 0.f);
                *(float2*)p = v;
            }
        }
    }
}

// ---------------------------------------------------------------------------
// Launcher: fork hgemm onto a second stream (graph-capturable via events)
// ---------------------------------------------------------------------------
extern "C" void kernel_launch(void* const* d_in, const int* in_sizes, int n_in,
                              void* d_out, int out_size)
{
    (void)in_sizes; (void)n_in; (void)out_size;

    const float* h          = (const float*)d_in[0];
    const float* norm       = (const float*)d_in[1];
    const float* rel_emb    = (const float*)d_in[2];
    const float* W_neighbor = (const float*)d_in[3];
    const float* loop_w     = (const float*)d_in[4];
    const int*   edge_src   = (const int*)d_in[5];
    const int*   edge_dst   = (const int*)d_in[6];
    const int*   edge_type  = (const int*)d_in[7];
    float*       out        = (float*)d_out;

    static cudaStream_t s2;
    static cudaEvent_t evFork, evJoin;
    static bool inited = false;
    if (!inited) {
        cudaStreamCreateWithFlags(&s2, cudaStreamNonBlocking);
        cudaEventCreateWithFlags(&evFork, cudaEventDisableTiming);
        cudaEventCreateWithFlags(&evJoin, cudaEventDisableTiming);
        cudaFuncSetAttribute(hgemm_kernel,
                             cudaFuncAttributeMaxDynamicSharedMemorySize, SM_TOTAL);
        cudaFuncSetAttribute(sgemm_kernel,
                             cudaFuncAttributeMaxDynamicSharedMemorySize, SM_TOTAL);
        inited = true;
    }

    // fork s2 off the (capturing) default stream
    cudaEventRecord(evFork, 0);
    cudaStreamWaitEvent(s2, evFork, 0);

    // stream 2: fully independent loop-message GEMM
    hgemm_kernel<<<NTILES, 256, SM_TOTAL, s2>>>(h, loop_w, out);
    cudaEventRecord(evJoin, s2);

    // default stream: init -> scatter
    init_kernel<<<1184, 256>>>(h, rel_emb, W_neighbor);
    {
        long long warps = (N_EDGES + 1) / 2;
        long long threads = warps * 32;
        scatter_edges_kernel<<<(int)((threads + 255) / 256), 256>>>(edge_src, edge_dst, edge_type);
    }

    // join, then fused S-GEMM epilogue
    cudaStreamWaitEvent(0, evJoin, 0);
    sgemm_kernel<<<NTILES, 256, SM_TOTAL>>>(norm, out);
}

// round 15
// speedup vs baseline: 1.4148x; 1.4148x over previous
#include <cuda_runtime.h>
#include <cuda_fp16.h>
#include <cstdint>

#define N_NODES 50000
#define N_EDGES 600000
#define N_RELS  500
#define DIM     128
#define M_PAD   50048
#define NTILES  391          // ceil(50000/128)
#define GRID_G  296          // 2 CTAs/SM * 148 SMs; CTA i does tiles i, i+296

typedef unsigned int u32;
typedef unsigned short u16;

// ---------------------------------------------------------------------------
// Device scratch (all fp16)
// ---------------------------------------------------------------------------
__device__ __align__(16) u16 g_S16[(size_t)M_PAD * DIM];      // fp16 scatter accumulator
__device__ __align__(16) u16 g_h16[(size_t)M_PAD * DIM];      // fp16 h (padded w/ zeros)
__device__ __align__(16) u16 g_rel16[N_RELS * DIM];           // fp16 rel_emb
__device__ __align__(16) u16 g_B[256 * DIM];                  // B=[Wn;Wl] fp16 [K=256][N=128]

__device__ __forceinline__ u32 pack_h2(float lo, float hi) {
    u32 r;
    asm("cvt.rn.f16x2.f32 %0, %1, %2;" : "=r"(r) : "f"(hi), "f"(lo));
    return r;
}

// ---------------------------------------------------------------------------
// Kernel 1: init, block-range partitioned, 4 uint4 items per thread (MLP).
//   blocks [0, 782)        zero g_S16            (800000 uint4)
//   blocks [782, 1565)     h -> fp16 (padded)    (800768 uint4)
//   blocks [1565, 1573)    rel_emb -> fp16       (8000 uint4)
//   blocks [1573, 1575)    B=[Wn;Wl] -> fp16     (4096 uint4)
// ---------------------------------------------------------------------------
#define ZB  782            // ceil(800000/1024)
#define HB  783            // ceil(800768/1024)
#define RB  8
#define WB  4              // 4096/1024
#define INIT_BLOCKS (ZB + HB + RB + WB)   // 1577

__global__ void __launch_bounds__(256) init_kernel(
    const float* __restrict__ h,
    const float* __restrict__ rel_emb,
    const float* __restrict__ W_neighbor,
    const float* __restrict__ loop_weight)
{
    int b = blockIdx.x;
    if (b < ZB) {
        int base = b * 1024 + threadIdx.x;
#pragma unroll
        for (int q = 0; q < 4; q++) {
            int i = base + q * 256;
            if (i < 800000) ((uint4*)g_S16)[i] = make_uint4(0, 0, 0, 0);
        }
    } else if (b < ZB + HB) {
        int base = (b - ZB) * 1024 + threadIdx.x;
#pragma unroll
        for (int q = 0; q < 4; q++) {
            int i = base + q * 256;
            if (i < 800768) {
                int row = i >> 4;
                int sg  = i & 15;
                uint4 o = make_uint4(0, 0, 0, 0);
                if (row < N_NODES) {
                    const float4* src = (const float4*)(h + (size_t)row * DIM + sg * 8);
                    float4 a = src[0], bb = src[1];
                    o.x = pack_h2(a.x, a.y);  o.y = pack_h2(a.z, a.w);
                    o.z = pack_h2(bb.x, bb.y); o.w = pack_h2(bb.z, bb.w);
                }
                ((uint4*)g_h16)[i] = o;
            }
        }
    } else if (b < ZB + HB + RB) {
        int base = (b - ZB - HB) * 1024 + threadIdx.x;
#pragma unroll
        for (int q = 0; q < 4; q++) {
            int i = base + q * 256;
            if (i < 8000) {
                const float4* src = (const float4*)(rel_emb + (size_t)i * 8);
                float4 a = src[0], bb = src[1];
                uint4 o;
                o.x = pack_h2(a.x, a.y);  o.y = pack_h2(a.z, a.w);
                o.z = pack_h2(bb.x, bb.y); o.w = pack_h2(bb.z, bb.w);
                ((uint4*)g_rel16)[i] = o;
            }
        }
    } else {
        int base = (b - ZB - HB - RB) * 1024 + threadIdx.x;
#pragma unroll
        for (int q = 0; q < 4; q++) {
            int i = base + q * 256;       // < 4096
            int k = i >> 4;
            int sg = i & 15;
            const float* src = (k < 128) ? (W_neighbor + (size_t)k * DIM + sg * 8)
                                         : (loop_weight + (size_t)(k - 128) * DIM + sg * 8);
            float4 a = ((const float4*)src)[0], bb = ((const float4*)src)[1];
            uint4 o;
            o.x = pack_h2(a.x, a.y);  o.y = pack_h2(a.z, a.w);
            o.z = pack_h2(bb.x, bb.y); o.w = pack_h2(bb.z, bb.w);
            ((uint4*)g_B)[i] = o;
        }
    }
}

// ---------------------------------------------------------------------------
// Kernel 2: fp16 edge scatter.  16 lanes per edge (one warp = 2 edges).
// ---------------------------------------------------------------------------
__global__ void __launch_bounds__(256) scatter_edges_kernel(
    const int* __restrict__ edge_src,
    const int* __restrict__ edge_dst,
    const int* __restrict__ edge_type)
{
    int w    = (int)((blockIdx.x * (unsigned)blockDim.x + threadIdx.x) >> 5);
    int lane = threadIdx.x & 31;
    int e    = w * 2 + (lane >> 4);
    if (e >= N_EDGES) return;
    int l16 = lane & 15;

    int s = __ldg(edge_src  + e);
    int d = __ldg(edge_dst  + e);
    int t = __ldg(edge_type + e);

    const uint4 hv = *(const uint4*)(g_h16   + (size_t)s * DIM + l16 * 8);
    const uint4 rv = *(const uint4*)(g_rel16 + (size_t)t * DIM + l16 * 8);

    u32 m0, m1, m2, m3;
    asm("add.rn.f16x2 %0, %1, %2;" : "=r"(m0) : "r"(hv.x), "r"(rv.x));
    asm("add.rn.f16x2 %0, %1, %2;" : "=r"(m1) : "r"(hv.y), "r"(rv.y));
    asm("add.rn.f16x2 %0, %1, %2;" : "=r"(m2) : "r"(hv.z), "r"(rv.z));
    asm("add.rn.f16x2 %0, %1, %2;" : "=r"(m3) : "r"(hv.w), "r"(rv.w));

    u16* outp = g_S16 + (size_t)d * DIM + l16 * 8;
    asm volatile("red.global.add.noftz.v4.f16x2 [%0], {%1, %2, %3, %4};"
                 :: "l"(outp), "r"(m0), "r"(m1), "r"(m2), "r"(m3) : "memory");
}

// ---------------------------------------------------------------------------
// Kernel 3: fused GEMM, fp16, persistent 296-CTA grid, 2-stage cp.async ring.
//   out = relu( norm .* (S @ Wn) + h @ Wl )
// K chunks 0-1 = S, 2-3 = h; norm applied to accumulators after chunk 1.
// CTA 256 thr / 8 warps, tile 128x128, warp 32x64.  2 CTAs/SM (71.7KB smem).
// Next tile's chunk 0/1 prefetch is issued before the epilogue stores.
// ---------------------------------------------------------------------------
#define A_STRIDE 144
#define B_STRIDE 272
#define OFF_A(s) ((s) * 18432)
#define OFF_B(s) (36864 + (s) * 17408)
#define SM_TOTAL 71680

__device__ __forceinline__ void ldsm4(u32* r, u32 addr) {
    asm volatile("ldmatrix.sync.aligned.m8n8.x4.shared.b16 {%0,%1,%2,%3}, [%4];"
                 : "=r"(r[0]), "=r"(r[1]), "=r"(r[2]), "=r"(r[3]) : "r"(addr));
}
__device__ __forceinline__ void ldsm4t(u32* r, u32 addr) {
    asm volatile("ldmatrix.sync.aligned.m8n8.x4.trans.shared.b16 {%0,%1,%2,%3}, [%4];"
                 : "=r"(r[0]), "=r"(r[1]), "=r"(r[2]), "=r"(r[3]) : "r"(addr));
}
__device__ __forceinline__ void mma16816(float* d, const u32* a, u32 b0, u32 b1) {
    asm volatile("mma.sync.aligned.m16n8k16.row.col.f32.f16.f16.f32 "
                 "{%0,%1,%2,%3}, {%4,%5,%6,%7}, {%8,%9}, {%0,%1,%2,%3};"
                 : "+f"(d[0]), "+f"(d[1]), "+f"(d[2]), "+f"(d[3])
                 : "r"(a[0]), "r"(a[1]), "r"(a[2]), "r"(a[3]), "r"(b0), "r"(b1));
}
__device__ __forceinline__ void cp16(u32 dst, const void* src) {
    asm volatile("cp.async.cg.shared.global [%0], [%1], 16;" :: "r"(dst), "l"(src) : "memory");
}
#define CP_COMMIT() asm volatile("cp.async.commit_group;" ::: "memory")

// cp.async A+B chunk c into stage s.  A source: S16 for c<2, h16 for c>=2.
__device__ __forceinline__ void issue_chunk(u32 sbase, int tid, int row0, int c, int s)
{
    const u16* asrc = (c < 2) ? g_S16 : g_h16;
    int koff = (c & 1) * 64;
    u32 ab = sbase + OFF_A(s);
#pragma unroll
    for (int it = 0; it < 4; it++) {
        int i  = tid + it * 256;           // < 1024
        int r  = i >> 3;
        int sg = i & 7;
        cp16(ab + (u32)(r * A_STRIDE + sg * 16),
             (const char*)(asrc + (size_t)(row0 + r) * DIM + koff) + sg * 16);
    }
    u32 bb = sbase + OFF_B(s);
#pragma unroll
    for (int it = 0; it < 4; it++) {
        int i  = tid + it * 256;           // < 1024
        int r  = i >> 4;
        int sg = i & 15;
        cp16(bb + (u32)(r * B_STRIDE + sg * 16),
             (const char*)g_B + (size_t)(c * 64 + r) * 256 + sg * 16);
    }
}

__global__ void __launch_bounds__(256, 2) gemm_fused_kernel(
    const float* __restrict__ norm,
    float* __restrict__ out)
{
    extern __shared__ char smem[];
    u32 sbase;
    asm("{ .reg .u64 t; cvta.to.shared.u64 t, %1; cvt.u32.u64 %0, t; }"
        : "=r"(sbase) : "l"(smem));

    const int tid    = threadIdx.x;
    const int wid    = tid >> 5;
    const int lane   = tid & 31;
    const int warp_m = wid & 3;
    const int warp_n = wid >> 2;

    // prologue for first tile
    {
        int row0 = blockIdx.x * 128;
        issue_chunk(sbase, tid, row0, 0, 0);
        CP_COMMIT();
        issue_chunk(sbase, tid, row0, 1, 1);
        CP_COMMIT();
    }

    for (int tile = blockIdx.x; tile < NTILES; tile += GRID_G) {
        const int row0 = tile * 128;

        float nrm[2][2];
#pragma unroll
        for (int mi = 0; mi < 2; mi++) {
            int r0 = row0 + warp_m * 32 + mi * 16 + (lane >> 2);
            nrm[mi][0] = (r0     < N_NODES) ? __ldg(norm + r0)     : 0.f;
            nrm[mi][1] = (r0 + 8 < N_NODES) ? __ldg(norm + r0 + 8) : 0.f;
        }

        float acc[2][8][4];
#pragma unroll
        for (int mi = 0; mi < 2; mi++)
#pragma unroll
            for (int ni = 0; ni < 8; ni++)
#pragma unroll
                for (int q = 0; q < 4; q++) acc[mi][ni][q] = 0.f;

#pragma unroll
        for (int c = 0; c < 4; c++) {
            const int s = c & 1;
            if (c < 3) asm volatile("cp.async.wait_group 1;" ::: "memory");
            else       asm volatile("cp.async.wait_group 0;" ::: "memory");
            __syncthreads();

            const u32 a_sm = sbase + OFF_A(s);
            const u32 b_sm = sbase + OFF_B(s);
#pragma unroll
            for (int k16 = 0; k16 < 4; k16++) {
                u32 bh[4][4];
#pragma unroll
                for (int ng = 0; ng < 4; ng++) {
                    u32 baddr = b_sm
                              + (u32)((k16 * 16 + (lane & 15)) * B_STRIDE)
                              + (u32)((warp_n * 64 + ng * 16 + (lane >> 4) * 8) * 2);
                    ldsm4t(bh[ng], baddr);
                }
#pragma unroll
                for (int mi = 0; mi < 2; mi++) {
                    u32 aaddr = a_sm
                              + (u32)((warp_m * 32 + mi * 16 + (lane & 15)) * A_STRIDE)
                              + (u32)(k16 * 32 + (lane >> 4) * 16);
                    u32 ah[4];
                    ldsm4(ah, aaddr);
#pragma unroll
                    for (int ni = 0; ni < 8; ni++) {
                        int ng = ni >> 1;
                        int hf = (ni & 1) * 2;
                        mma16816(acc[mi][ni], ah, bh[ng][hf], bh[ng][hf + 1]);
                    }
                }
            }

            if (c == 1) {
#pragma unroll
                for (int mi = 0; mi < 2; mi++)
#pragma unroll
                    for (int ni = 0; ni < 8; ni++) {
                        acc[mi][ni][0] *= nrm[mi][0];
                        acc[mi][ni][1] *= nrm[mi][0];
                        acc[mi][ni][2] *= nrm[mi][1];
                        acc[mi][ni][3] *= nrm[mi][1];
                    }
            }

            if (c < 2) {
                __syncthreads();
                issue_chunk(sbase, tid, row0, c + 2, s);
                CP_COMMIT();
            }
        }

        // all warps done reading smem for this tile; prefetch next tile's
        // chunks 0/1 so the cp.asyncs overlap the epilogue stores below.
        __syncthreads();
        int ntile = tile + GRID_G;
        if (ntile < NTILES) {
            int nrow0 = ntile * 128;
            issue_chunk(sbase, tid, nrow0, 0, 0);
            CP_COMMIT();
            issue_chunk(sbase, tid, nrow0, 1, 1);
            CP_COMMIT();
        }

        // epilogue: relu + store (32x64 per warp)
#pragma unroll
        for (int mi = 0; mi < 2; mi++) {
            int r0 = row0 + warp_m * 32 + mi * 16 + (lane >> 2);
#pragma unroll
            for (int ni = 0; ni < 8; ni++) {
                int col = warp_n * 64 + ni * 8 + (lane & 3) * 2;
                if (r0 < N_NODES) {
                    float2 v;
                    v.x = fmaxf(acc[mi][ni][0], 0.f);
                    v.y = fmaxf(acc[mi][ni][1], 0.f);
                    *(float2*)(out + (size_t)r0 * DIM + col) = v;
                }
                if (r0 + 8 < N_NODES) {
                    float2 v;
                    v.x = fmaxf(acc[mi][ni][2], 0.f);
                    v.y = fmaxf(acc[mi][ni][3], 0.f);
                    *(float2*)(out + (size_t)(r0 + 8) * DIM + col) = v;
                }
            }
        }
    }
}

// ---------------------------------------------------------------------------
// Launcher
// ---------------------------------------------------------------------------
extern "C" void kernel_launch(void* const* d_in, const int* in_sizes, int n_in,
                              void* d_out, int out_size)
{
    (void)in_sizes; (void)n_in; (void)out_size;

    const float* h          = (const float*)d_in[0];
    const float* norm       = (const float*)d_in[1];
    const float* rel_emb    = (const float*)d_in[2];
    const float* W_neighbor = (const float*)d_in[3];
    const float* loop_w     = (const float*)d_in[4];
    const int*   edge_src   = (const int*)d_in[5];
    const int*   edge_dst   = (const int*)d_in[6];
    const int*   edge_type  = (const int*)d_in[7];
    float*       out        = (float*)d_out;

    init_kernel<<<INIT_BLOCKS, 256>>>(h, rel_emb, W_neighbor, loop_w);
    {
        long long warps = (N_EDGES + 1) / 2;
        long long threads = warps * 32;
        scatter_edges_kernel<<<(int)((threads + 255) / 256), 256>>>(edge_src, edge_dst, edge_type);
    }
    {
        static bool attr_set = false;
        if (!attr_set) {
            cudaFuncSetAttribute(gemm_fused_kernel,
                                 cudaFuncAttributeMaxDynamicSharedMemorySize, SM_TOTAL);
            attr_set = true;
        }
        gemm_fused_kernel<<<GRID_G, 256, SM_TOTAL>>>(norm, out);
    }
}